// round 13
// baseline (speedup 1.0000x reference)
#include <cuda_runtime.h>
#include <cuda_bf16.h>
#include <cstdint>
#include <math.h>

// ---------------- problem constants ----------------
#define MM 2048      // num_memories
#define DD 7686      // input size
#define HH 512
#define OO 8
#define NN 8206      // DD + HH + OO
#define KP 7744      // K padded to multiple of 32
#define WROWS 7808   // padded B rows for W^T (61 * 128)
#define BKC 32
#define KCHUNKS (KP / BKC)   // 242

// ---------------- small PTX helpers ----------------
__device__ __forceinline__ uint32_t smem_to_u32(const void* p) {
    uint32_t a;
    asm("{ .reg .u64 t; cvta.to.shared.u64 t, %1; cvt.u32.u64 %0, t; }"
        : "=r"(a) : "l"(p));
    return a;
}

__device__ __forceinline__ void cpa16(uint32_t s, const void* g) {
    asm volatile("cp.async.cg.shared.global [%0], [%1], 16;" :: "r"(s), "l"(g) : "memory");
}

__device__ __forceinline__ void ldsm4(uint32_t (&r)[4], uint32_t addr) {
    asm volatile("ldmatrix.sync.aligned.m8n8.x4.shared.b16 {%0,%1,%2,%3}, [%4];"
                 : "=r"(r[0]), "=r"(r[1]), "=r"(r[2]), "=r"(r[3]) : "r"(addr));
}

__device__ __forceinline__ void mma16816(float (&d)[4], const uint32_t (&a)[4],
                                         const uint32_t b0, const uint32_t b1) {
    asm volatile(
        "mma.sync.aligned.m16n8k16.row.col.f32.bf16.bf16.f32 "
        "{%0,%1,%2,%3}, {%4,%5,%6,%7}, {%8,%9}, {%0,%1,%2,%3};"
        : "+f"(d[0]), "+f"(d[1]), "+f"(d[2]), "+f"(d[3])
        : "r"(a[0]), "r"(a[1]), "r"(a[2]), "r"(a[3]), "r"(b0), "r"(b1));
}

// SW64 swizzle for 64B-wide smem rows (conflict-free ldmatrix)
__device__ __forceinline__ uint32_t sw_off(int row, int c) {
    uint32_t o = (uint32_t)(row * 64 + c * 16);
    return o ^ ((o >> 3) & 0x30);
}

// ---- mbarrier ops (sm_80 / sm_90 PTX, valid on compute_103) ----
#define MBARRIER_INIT(mbar, cnt) \
    asm volatile("mbarrier.init.shared.b64 [%0], %1;" \
                 :: "r"((uint32_t)(mbar)), "r"((uint32_t)(cnt)) : "memory")

__device__ __forceinline__ void mbar_arrive(uint32_t a) {
    asm volatile("{\n\t.reg .b64 tk;\n\tmbarrier.arrive.shared.b64 tk, [%0];\n\t}"
                 :: "r"(a) : "memory");
}

// deferred arrive: fires when all prior cp.async of this thread have completed
__device__ __forceinline__ void cpasync_arrive_noinc(uint32_t a) {
    asm volatile("cp.async.mbarrier.arrive.noinc.shared.b64 [%0];" :: "r"(a) : "memory");
}

#define MBARRIER_WAIT_PARITY(mbar_smem_addr, phase_parity) do { \
    uint32_t _mbar = (uint32_t)(mbar_smem_addr); \
    uint32_t _parity = (uint32_t)(phase_parity); \
    uint32_t _done; \
    asm volatile( \
        "{\n\t.reg .pred p;\n\t" \
        "mbarrier.try_wait.parity.shared.b64 p, [%1], %2;\n\t" \
        "selp.b32 %0, 1, 0, p;\n\t}" \
        : "=r"(_done) : "r"(_mbar), "r"(_parity) : "memory"); \
    if (!_done) { \
        asm volatile( \
            "{\n\t.reg .pred P1;\n\t" \
            "WAIT_LOOP_%=:\n\t" \
            "mbarrier.try_wait.parity.shared.b64 P1, [%0], %1, 0x989680;\n\t" \
            "@P1 bra.uni WAIT_DONE_%=;\n\t" \
            "bra.uni WAIT_LOOP_%=;\n\t" \
            "WAIT_DONE_%=:\n\t}" \
            :: "r"(_mbar), "r"(_parity) : "memory"); \
    } \
} while(0)

// ---------------- device scratch ----------------
__device__ __nv_bfloat16 g_ihi[(size_t)MM * KP];
__device__ __nv_bfloat16 g_ilo[(size_t)MM * KP];
__device__ __nv_bfloat16 g_wtqhi[(size_t)WROWS * KP];
__device__ __nv_bfloat16 g_wtqlo[(size_t)WROWS * KP];
__device__ __nv_bfloat16 g_wtkhi[(size_t)WROWS * KP];
__device__ __nv_bfloat16 g_wtklo[(size_t)WROWS * KP];
__device__ __nv_bfloat16 g_qhi[(size_t)MM * KP];
__device__ __nv_bfloat16 g_qlo[(size_t)MM * KP];
__device__ __nv_bfloat16 g_khi[(size_t)MM * KP];
__device__ __nv_bfloat16 g_klo[(size_t)MM * KP];
__device__ float g_scores[(size_t)MM * MM];
__device__ float g_cs_part[16 * MM];
__device__ float g_colsum[MM];
__device__ float g_part[16 * DD];
__device__ float g_u[DD];
__device__ float g_context[DD];
__device__ float g_s1_part[61 * (HH + OO)];
__device__ float g_vals1[HH + OO];
__device__ float g_s2_part[32 * OO];

// ---------------- split fp32 -> bf16 hi/lo, pad cols to KP (8B stores) ----------
__global__ void split_pad(const float* __restrict__ x,
                          __nv_bfloat16* __restrict__ hi,
                          __nv_bfloat16* __restrict__ lo, int cols)
{
    int c = (blockIdx.x * 256 + threadIdx.x) * 4;
    if (c >= KP) return;
    int r = blockIdx.y;
    const float* xr = x + (size_t)r * cols;
    uint32_t hw[2], lw[2];
    #pragma unroll
    for (int j = 0; j < 2; ++j) {
        float v0 = (c + 2*j     < cols) ? xr[c + 2*j]     : 0.f;
        float v1 = (c + 2*j + 1 < cols) ? xr[c + 2*j + 1] : 0.f;
        __nv_bfloat16 h0 = __float2bfloat16(v0);
        __nv_bfloat16 h1 = __float2bfloat16(v1);
        __nv_bfloat162 hp; hp.x = h0; hp.y = h1;
        __nv_bfloat162 lp;
        lp.x = __float2bfloat16(v0 - __bfloat162float(h0));
        lp.y = __float2bfloat16(v1 - __bfloat162float(h1));
        hw[j] = *(uint32_t*)&hp;
        lw[j] = *(uint32_t*)&lp;
    }
    *(uint2*)(hi + (size_t)r * KP + c) = make_uint2(hw[0], hw[1]);
    *(uint2*)(lo + (size_t)r * KP + c) = make_uint2(lw[0], lw[1]);
}

// ---------------- transpose + split: W[k][n] -> Wt[n][k] bf16 hi/lo -------------
__global__ void transpose_split(const float* __restrict__ W,
                                __nv_bfloat16* __restrict__ Thi,
                                __nv_bfloat16* __restrict__ Tlo)
{
    __shared__ float s[32][33];
    const int t = threadIdx.x;
    const int n0 = blockIdx.x * 32;
    const int k0 = blockIdx.y * 32;

    #pragma unroll
    for (int i = 0; i < 4; ++i) {
        int idx = i * 256 + t;
        int kl = idx >> 5, nl = idx & 31;
        int k = k0 + kl, n = n0 + nl;
        s[kl][nl] = (k < DD && n < DD) ? W[(size_t)k * DD + n] : 0.f;
    }
    __syncthreads();

    const int a = t >> 3;          // n-local 0..31
    const int g = (t & 7) * 4;     // k-group
    uint32_t hw[2], lw[2];
    #pragma unroll
    for (int j = 0; j < 2; ++j) {
        float v0 = s[g + 2*j][a];
        float v1 = s[g + 2*j + 1][a];
        __nv_bfloat16 h0 = __float2bfloat16(v0);
        __nv_bfloat16 h1 = __float2bfloat16(v1);
        __nv_bfloat162 hp; hp.x = h0; hp.y = h1;
        __nv_bfloat162 lp;
        lp.x = __float2bfloat16(v0 - __bfloat162float(h0));
        lp.y = __float2bfloat16(v1 - __bfloat162float(h1));
        hw[j] = *(uint32_t*)&hp;
        lw[j] = *(uint32_t*)&lp;
    }
    size_t off = (size_t)(n0 + a) * KP + (k0 + g);
    *(uint2*)(Thi + off) = make_uint2(hw[0], hw[1]);
    *(uint2*)(Tlo + off) = make_uint2(lw[0], lw[1]);
}

// ---------------- bf16x3 mma.sync GEMM, CTA tile 128x128, 4 warps ---------------
// Dual-B dispatch (q & k fused). mbarrier producer/consumer ring replaces the
// per-chunk __syncthreads: full[s] via cp.async.mbarrier.arrive (deferred HW
// arrive when copies land), empty[s] via reader arrives. Warps free-run,
// coupled only at stage distance 2. Per-accumulator op sequence unchanged
// => bit-identical results.
#define T_AHI 0
#define T_ALO 8192
#define T_BHI 16384
#define T_BLO 24576
#define STAGE_BYTES 32768
#define NSTAGE 3
#define SMEM_GEMM (NSTAGE * STAGE_BYTES + 128)   // stages + mbarriers

__global__ __launch_bounds__(128, 2)
void tc_gemm(const __nv_bfloat16* __restrict__ Ahi, const __nv_bfloat16* __restrict__ Alo,
             const __nv_bfloat16* __restrict__ B1hi, const __nv_bfloat16* __restrict__ B1lo,
             const __nv_bfloat16* __restrict__ B2hi, const __nv_bfloat16* __restrict__ B2lo,
             const float* __restrict__ bias1, const float* __restrict__ bias2,
             int nsplit, float scale,
             float* __restrict__ Cf, int Cld,
             __nv_bfloat16* __restrict__ C1hi, __nv_bfloat16* __restrict__ C1lo,
             __nv_bfloat16* __restrict__ C2hi, __nv_bfloat16* __restrict__ C2lo)
{
    extern __shared__ char smem[];
    const uint32_t sb = smem_to_u32(smem);
    const uint32_t mb = sb + NSTAGE * STAGE_BYTES;   // mbarrier block
    const int t   = threadIdx.x;
    const int wid = t >> 5;
    const int lid = t & 31;
    const int m0 = blockIdx.y * 128;

    const __nv_bfloat16 *Bhi, *Blo;
    const float* bias;
    __nv_bfloat16 *Chi, *Clo;
    int n0;
    if ((int)blockIdx.x < nsplit) {
        n0 = blockIdx.x * 128;
        Bhi = B1hi; Blo = B1lo; bias = bias1; Chi = C1hi; Clo = C1lo;
    } else {
        n0 = (blockIdx.x - nsplit) * 128;
        Bhi = B2hi; Blo = B2lo; bias = bias2; Chi = C2hi; Clo = C2lo;
    }

    // mbarrier layout: [full0, empty0, full1, empty1, full2, empty2], 8B each
    if (t == 0) {
        #pragma unroll
        for (int s = 0; s < NSTAGE; ++s) {
            MBARRIER_INIT(mb + s * 16,     128);  // full
            MBARRIER_INIT(mb + s * 16 + 8, 128);  // empty
        }
    }
    __syncthreads();

    const int rl = t >> 2;
    const int cl = t & 3;
    const uint32_t soR[4] = { sw_off(rl, cl), sw_off(rl + 32, cl),
                              sw_off(rl + 64, cl), sw_off(rl + 96, cl) };

    float acc[4][8][4];
    #pragma unroll
    for (int a = 0; a < 4; ++a)
        #pragma unroll
        for (int b = 0; b < 8; ++b)
            #pragma unroll
            for (int c = 0; c < 4; ++c) acc[a][b][c] = 0.f;

    const char* pAhi = (const char*)Ahi;
    const char* pAlo = (const char*)Alo;
    const char* pBhi = (const char*)Bhi;
    const char* pBlo = (const char*)Blo;

    // full-burst loader (priming only)
    auto load_stage = [&](int kc, int slot) {
        const int k0 = kc * BKC;
        const uint32_t st = sb + slot * STAGE_BYTES;
        #pragma unroll
        for (int i = 0; i < 4; ++i) {
            const int r = rl + 32 * i;
            size_t ga = (((size_t)(m0 + r) * KP + k0 + cl * 8) << 1);
            size_t gb = (((size_t)(n0 + r) * KP + k0 + cl * 8) << 1);
            cpa16(st + T_AHI + soR[i], pAhi + ga);
            cpa16(st + T_ALO + soR[i], pAlo + ga);
            cpa16(st + T_BHI + soR[i], pBhi + gb);
            cpa16(st + T_BLO + soR[i], pBlo + gb);
        }
    };

    const int wm = wid >> 1;       // 0..1 (m offset 64)
    const int wn = wid & 1;        // 0..1 (n offset 64)
    const int lrow = lid & 15;
    const int lcg  = lid >> 4;     // 0..1

    load_stage(0, 0);
    cpasync_arrive_noinc(mb + 0 * 16);       // full[0]
    load_stage(1, 1);
    cpasync_arrive_noinc(mb + 1 * 16);       // full[1]

    int slot = 0;                  // kc % 3
    int nslot = 2;                 // (kc+2) % 3
    for (int kc = 0; kc < KCHUNKS; ++kc) {
        const int cur = slot;
        const int tau = nslot;
        slot = (slot == 2) ? 0 : slot + 1;
        nslot = (nslot == 2) ? 0 : nslot + 1;

        // consumer: wait for stage cur to be filled (round kc/3)
        MBARRIER_WAIT_PARITY(mb + cur * 16, (uint32_t)((kc / 3) & 1));

        const bool pf = (kc + 2 < KCHUNKS);
        const int pk0 = (kc + 2) * BKC;
        const uint32_t pst = sb + tau * STAGE_BYTES;
        const uint32_t st = sb + cur * STAGE_BYTES;

        auto load_slice = [&](int i) {
            if (pf) {
                const int r = rl + 32 * i;
                size_t ga = (((size_t)(m0 + r) * KP + pk0 + cl * 8) << 1);
                size_t gb = (((size_t)(n0 + r) * KP + pk0 + cl * 8) << 1);
                cpa16(pst + T_AHI + soR[i], pAhi + ga);
                cpa16(pst + T_ALO + soR[i], pAlo + ga);
                cpa16(pst + T_BHI + soR[i], pBhi + gb);
                cpa16(pst + T_BLO + soR[i], pBlo + gb);
            }
        };

        #pragma unroll
        for (int ks = 0; ks < 2; ++ks) {
            const int ccol = ks * 2 + lcg;
            uint32_t ahi[4][4], alo[4][4];
            uint32_t bhi[8][2], blo[8][2];

            // minimal preload: A-hi fragments + first B-hi pair
            #pragma unroll
            for (int mt = 0; mt < 4; ++mt)
                ldsm4(ahi[mt], st + T_AHI + sw_off(wm * 64 + mt * 16 + lrow, ccol));
            {
                uint32_t r[4];
                ldsm4(r, st + T_BHI + sw_off(wn * 64 + lrow, ccol));
                bhi[0][0] = r[0]; bhi[0][1] = r[2];
                bhi[1][0] = r[1]; bhi[1][1] = r[3];
            }

            // pass 1: hi*hi  (prefetch remaining bhi + all blo under mma)
            #pragma unroll
            for (int p = 0; p < 4; ++p) {
                if (p < 3) {
                    uint32_t r[4];
                    ldsm4(r, st + T_BHI + sw_off(wn * 64 + (p + 1) * 16 + lrow, ccol));
                    bhi[2*p+2][0] = r[0]; bhi[2*p+2][1] = r[2];
                    bhi[2*p+3][0] = r[1]; bhi[2*p+3][1] = r[3];
                }
                {
                    uint32_t r[4];
                    ldsm4(r, st + T_BLO + sw_off(wn * 64 + p * 16 + lrow, ccol));
                    blo[2*p][0] = r[0]; blo[2*p][1] = r[2];
                    blo[2*p+1][0] = r[1]; blo[2*p+1][1] = r[3];
                }
                #pragma unroll
                for (int mt = 0; mt < 4; ++mt) {
                    mma16816(acc[mt][2*p],     ahi[mt], bhi[2*p][0],   bhi[2*p][1]);
                    mma16816(acc[mt][2*p + 1], ahi[mt], bhi[2*p+1][0], bhi[2*p+1][1]);
                }
            }

            // producer: before first write to stage tau, wait its readers
            if (ks == 0 && pf && kc >= 1)
                MBARRIER_WAIT_PARITY(mb + tau * 16 + 8,
                                     (uint32_t)(((kc - 1) / 3) & 1));

            // pass 2: hi*lo  (prefetch alo under mma; inject cp.async slice)
            load_slice(ks * 2);
            #pragma unroll
            for (int p = 0; p < 4; ++p) {
                ldsm4(alo[p], st + T_ALO + sw_off(wm * 64 + p * 16 + lrow, ccol));
                #pragma unroll
                for (int mt = 0; mt < 4; ++mt) {
                    mma16816(acc[mt][2*p],     ahi[mt], blo[2*p][0],   blo[2*p][1]);
                    mma16816(acc[mt][2*p + 1], ahi[mt], blo[2*p+1][0], blo[2*p+1][1]);
                }
            }

            // pass 3: lo*hi  (pure mma; inject second cp.async slice)
            load_slice(ks * 2 + 1);
            #pragma unroll
            for (int mt = 0; mt < 4; ++mt)
                #pragma unroll
                for (int q = 0; q < 8; ++q)
                    mma16816(acc[mt][q], alo[mt], bhi[q][0], bhi[q][1]);
        }

        // reader done with stage cur; producer arrive for stage tau fill
        mbar_arrive(mb + cur * 16 + 8);
        if (pf) cpasync_arrive_noinc(mb + tau * 16);
    }

    // ---- epilogue ----
    const int g  = lid >> 2;
    const int t4 = lid & 3;
    #pragma unroll
    for (int mt = 0; mt < 4; ++mt) {
        #pragma unroll
        for (int nt = 0; nt < 8; ++nt) {
            const int m = m0 + wm * 64 + mt * 16 + g;
            const int n = n0 + wn * 64 + nt * 8 + t4 * 2;
            float d0 = acc[mt][nt][0], d1 = acc[mt][nt][1];
            float d2 = acc[mt][nt][2], d3 = acc[mt][nt][3];
            if (Cf) {
                if (n + 1 < Cld) {
                    float2 v0 = make_float2(d0 * scale, d1 * scale);
                    float2 v1 = make_float2(d2 * scale, d3 * scale);
                    *(float2*)(Cf + (size_t)m * Cld + n) = v0;
                    *(float2*)(Cf + (size_t)(m + 8) * Cld + n) = v1;
                }
            } else {
                if (n < KP) {
                    float b0 = (n     < DD) ? bias[n]     : 0.f;
                    float b1 = (n + 1 < DD) ? bias[n + 1] : 0.f;
                    float v0 = (n     < DD) ? d0 + b0 : 0.f;
                    float v1 = (n + 1 < DD) ? d1 + b1 : 0.f;
                    float v2 = (n     < DD) ? d2 + b0 : 0.f;
                    float v3 = (n + 1 < DD) ? d3 + b1 : 0.f;
                    __nv_bfloat16 h0 = __float2bfloat16(v0);
                    __nv_bfloat16 h1 = __float2bfloat16(v1);
                    __nv_bfloat16 h2 = __float2bfloat16(v2);
                    __nv_bfloat16 h3 = __float2bfloat16(v3);
                    __nv_bfloat162 hp0; hp0.x = h0; hp0.y = h1;
                    __nv_bfloat162 hp1; hp1.x = h2; hp1.y = h3;
                    __nv_bfloat162 lp0;
                    lp0.x = __float2bfloat16(v0 - __bfloat162float(h0));
                    lp0.y = __float2bfloat16(v1 - __bfloat162float(h1));
                    __nv_bfloat162 lp1;
                    lp1.x = __float2bfloat16(v2 - __bfloat162float(h2));
                    lp1.y = __float2bfloat16(v3 - __bfloat162float(h3));
                    *(__nv_bfloat162*)(Chi + (size_t)m * KP + n) = hp0;
                    *(__nv_bfloat162*)(Chi + (size_t)(m + 8) * KP + n) = hp1;
                    *(__nv_bfloat162*)(Clo + (size_t)m * KP + n) = lp0;
                    *(__nv_bfloat162*)(Clo + (size_t)(m + 8) * KP + n) = lp1;
                }
            }
        }
    }
}

// ---------------- row softmax (in place), row length MM ------------------------
__global__ void softmax_rows(float* __restrict__ S)
{
    const int row = blockIdx.x;
    const int t = threadIdx.x;
    float* r = S + (size_t)row * MM;
    float v[8];
    #pragma unroll
    for (int i = 0; i < 8; ++i) v[i] = r[i * 256 + t];

    float mx = v[0];
    #pragma unroll
    for (int i = 1; i < 8; ++i) mx = fmaxf(mx, v[i]);

    __shared__ float sh[32];
    #pragma unroll
    for (int o = 16; o > 0; o >>= 1) mx = fmaxf(mx, __shfl_xor_sync(0xffffffff, mx, o));
    if ((t & 31) == 0) sh[t >> 5] = mx;
    __syncthreads();
    if (t < 32) {
        float m = (t < 8) ? sh[t] : -INFINITY;
        #pragma unroll
        for (int o = 4; o > 0; o >>= 1) m = fmaxf(m, __shfl_xor_sync(0xffffffff, m, o));
        sh[0] = m;
    }
    __syncthreads();
    mx = sh[0];
    __syncthreads();

    float sum = 0.f;
    #pragma unroll
    for (int i = 0; i < 8; ++i) { v[i] = expf(v[i] - mx); sum += v[i]; }
    #pragma unroll
    for (int o = 16; o > 0; o >>= 1) sum += __shfl_xor_sync(0xffffffff, sum, o);
    if ((t & 31) == 0) sh[t >> 5] = sum;
    __syncthreads();
    if (t < 32) {
        float s = (t < 8) ? sh[t] : 0.f;
        #pragma unroll
        for (int o = 4; o > 0; o >>= 1) s += __shfl_xor_sync(0xffffffff, s, o);
        sh[0] = s;
    }
    __syncthreads();
    float inv = 1.f / sh[0];
    #pragma unroll
    for (int i = 0; i < 8; ++i) r[i * 256 + t] = v[i] * inv;
}

// ---------------- column sums of P ----------------
__global__ void colsum_part(const float* __restrict__ P)
{
    int j = blockIdx.x * 256 + threadIdx.x;
    int r0 = blockIdx.y * 128;
    float acc = 0.f;
    for (int r = 0; r < 128; ++r) acc += P[(size_t)(r0 + r) * MM + j];
    g_cs_part[blockIdx.y * MM + j] = acc;
}

__global__ void colsum_reduce()
{
    int j = blockIdx.x * 256 + threadIdx.x;
    float acc = 0.f;
    #pragma unroll
    for (int c = 0; c < 16; ++c) acc += g_cs_part[c * MM + j];
    g_colsum[j] = acc;
}

// ---------------- u = (colsum @ inp) / M ----------------
__global__ void u_part(const float* __restrict__ X)
{
    int j = blockIdx.x * 256 + threadIdx.x;
    if (j >= DD) return;
    int r0 = blockIdx.y * 128;
    float acc = 0.f;
    for (int r = 0; r < 128; ++r) {
        int l = r0 + r;
        acc += g_colsum[l] * X[(size_t)l * DD + j];
    }
    g_part[blockIdx.y * DD + j] = acc;
}

__global__ void u_reduce()
{
    int j = blockIdx.x * 256 + threadIdx.x;
    if (j >= DD) return;
    float acc = 0.f;
    #pragma unroll
    for (int c = 0; c < 16; ++c) acc += g_part[c * DD + j];
    g_u[j] = acc * (1.0f / (float)MM);
}

// ---------------- context = u @ Wv + bv ----------------
__global__ void ctx2_part(const float* __restrict__ Wv)
{
    int j = blockIdx.x * 256 + threadIdx.x;
    if (j >= DD) return;
    int i0 = blockIdx.y * 481;
    float acc = 0.f;
    for (int r = 0; r < 481; ++r) {
        int i = i0 + r;
        if (i < DD) acc += g_u[i] * Wv[(size_t)i * DD + j];
    }
    g_part[blockIdx.y * DD + j] = acc;
}

__global__ void ctx2_reduce(const float* __restrict__ bv)
{
    int j = blockIdx.x * 256 + threadIdx.x;
    if (j >= DD) return;
    float acc = 0.f;
    #pragma unroll
    for (int c = 0; c < 16; ++c) acc += g_part[c * DD + j];
    g_context[j] = acc + bv[j];
}

// ---------------- sweep 1: cols [DD, NN), rows i<DD ----------------
__global__ void sweep1_part(const float* __restrict__ mu, const float* __restrict__ sig,
                            const float* __restrict__ eps)
{
    int jj = blockIdx.x * 256 + threadIdx.x;
    if (jj >= HH + OO) return;
    int j = DD + jj;
    int i0 = blockIdx.y * 126;
    float acc = 0.f;
    for (int r = 0; r < 126; ++r) {
        int i = i0 + r;
        size_t off = (size_t)i * NN + j;
        acc += g_context[i] * (mu[off] + sig[off] * eps[off]);
    }
    g_s1_part[blockIdx.y * (HH + OO) + jj] = acc;
}

__global__ void sweep1_final(const float* __restrict__ bmu, const float* __restrict__ bsig,
                             const float* __restrict__ epsb)
{
    int jj = blockIdx.x * 256 + threadIdx.x;
    if (jj >= HH + OO) return;
    int j = DD + jj;
    float acc = 0.f;
    for (int c = 0; c < 61; ++c) acc += g_s1_part[c * (HH + OO) + jj];
    g_vals1[jj] = tanhf(acc + bmu[j] + bsig[j] * epsb[j]);
}

// ---------------- sweep 2: cols [DD+HH, NN), all rows ----------------
__global__ void sweep2_part(const float* __restrict__ mu, const float* __restrict__ sig,
                            const float* __restrict__ eps)
{
    const int t = threadIdx.x;
    const int col = t & 7;
    const int lane = t >> 3;
    const int i0 = blockIdx.x * 257;
    const int j = DD + HH + col;
    float acc = 0.f;
    for (int r = lane; r < 257; r += 32) {
        int i = i0 + r;
        if (i < NN) {
            float vi = (i < DD) ? g_context[i] : g_vals1[i - DD];
            size_t off = (size_t)i * NN + j;
            acc += vi * (mu[off] + sig[off] * eps[off]);
        }
    }
    __shared__ float sh[256];
    sh[t] = acc;
    __syncthreads();
    for (int s = 128; s >= 8; s >>= 1) {
        if (t < s) sh[t] += sh[t + s];
        __syncthreads();
    }
    if (t < 8) g_s2_part[blockIdx.x * 8 + t] = sh[t];
}

__global__ void final_out(const float* __restrict__ bmu, const float* __restrict__ bsig,
                          const float* __restrict__ epsb, float* __restrict__ out)
{
    int t = threadIdx.x;
    if (t < OO) {
        float acc = 0.f;
        #pragma unroll
        for (int b = 0; b < 32; ++b) acc += g_s2_part[b * 8 + t];
        int j = DD + HH + t;
        float v = tanhf(acc + bmu[j] + bsig[j] * epsb[j]);
        out[t] = 1.0f / (1.0f + expf(-v));
    }
}

// ---------------- launcher -------------------------------------------------------
extern "C" void kernel_launch(void* const* d_in, const int* in_sizes, int n_in,
                              void* d_out, int out_size)
{
    const float* inp  = (const float*)d_in[0];
    const float* Wq   = (const float*)d_in[1];
    const float* bq   = (const float*)d_in[2];
    const float* Wk   = (const float*)d_in[3];
    const float* bk   = (const float*)d_in[4];
    const float* Wv   = (const float*)d_in[5];
    const float* bv   = (const float*)d_in[6];
    const float* wmu  = (const float*)d_in[7];
    const float* wsig = (const float*)d_in[8];
    const float* bmu  = (const float*)d_in[9];
    const float* bsig = (const float*)d_in[10];
    const float* epsw = (const float*)d_in[11];
    const float* epsb = (const float*)d_in[12];
    float* out = (float*)d_out;

    __nv_bfloat16 *ihi, *ilo, *wtqhi, *wtqlo, *wtkhi, *wtklo;
    __nv_bfloat16 *qhi, *qlo, *khi, *klo;
    float *sc;
    cudaGetSymbolAddress((void**)&ihi,   g_ihi);
    cudaGetSymbolAddress((void**)&ilo,   g_ilo);
    cudaGetSymbolAddress((void**)&wtqhi, g_wtqhi);
    cudaGetSymbolAddress((void**)&wtqlo, g_wtqlo);
    cudaGetSymbolAddress((void**)&wtkhi, g_wtkhi);
    cudaGetSymbolAddress((void**)&wtklo, g_wtklo);
    cudaGetSymbolAddress((void**)&qhi,   g_qhi);
    cudaGetSymbolAddress((void**)&qlo,   g_qlo);
    cudaGetSymbolAddress((void**)&khi,   g_khi);
    cudaGetSymbolAddress((void**)&klo,   g_klo);
    cudaGetSymbolAddress((void**)&sc,    g_scores);

    cudaFuncSetAttribute(tc_gemm, cudaFuncAttributeMaxDynamicSharedMemorySize,
                         SMEM_GEMM);

    const dim3 split_grid((KP / 4 + 255) / 256, MM);
    const dim3 tr_grid(WROWS / 32, KP / 32);
    const dim3 qk_grid(2 * (WROWS / 128), MM / 128);   // 122 x 16 (q & k fused)
    const dim3 sc_grid(MM / 128, MM / 128);            // 16 x 16

    // input split to bf16 hi/lo
    split_pad<<<split_grid, 256>>>(inp, ihi, ilo, DD);

    // transpose+split both weight matrices
    transpose_split<<<tr_grid, 256>>>(Wq, wtqhi, wtqlo);
    transpose_split<<<tr_grid, 256>>>(Wk, wtkhi, wtklo);

    // q = inp @ Wq + bq  AND  k = inp @ Wk + bk  (one launch, bf16 hi/lo out)
    tc_gemm<<<qk_grid, 128, SMEM_GEMM>>>(ihi, ilo,
                                         wtqhi, wtqlo, wtkhi, wtklo,
                                         bq, bk, WROWS / 128, 1.f,
                                         nullptr, 0, qhi, qlo, khi, klo);

    // scores = q @ k^T / sqrt(D)  (fp32 out)
    tc_gemm<<<sc_grid, 128, SMEM_GEMM>>>(qhi, qlo,
                                         khi, klo, nullptr, nullptr,
                                         nullptr, nullptr, 1 << 20,
                                         rsqrtf((float)DD),
                                         sc, MM, nullptr, nullptr, nullptr, nullptr);

    softmax_rows<<<MM, 256>>>(sc);

    colsum_part<<<dim3(MM / 256, 16), 256>>>(sc);
    colsum_reduce<<<MM / 256, 256>>>();

    // context = ((colsum/M) @ inp) @ Wv + bv
    u_part<<<dim3((DD + 255) / 256, 16), 256>>>(inp);
    u_reduce<<<(DD + 255) / 256, 256>>>();
    ctx2_part<<<dim3((DD + 255) / 256, 16), 256>>>(Wv);
    ctx2_reduce<<<(DD + 255) / 256, 256>>>(bv);

    sweep1_part<<<dim3(3, 61), 256>>>(wmu, wsig, epsw);
    sweep1_final<<<3, 256>>>(bmu, bsig, epsb);

    sweep2_part<<<32, 256>>>(wmu, wsig, epsw);
    final_out<<<1, 32>>>(bmu, bsig, epsb, out);
}

// round 14
// speedup vs baseline: 1.0258x; 1.0258x over previous
#include <cuda_runtime.h>
#include <cuda_bf16.h>
#include <cstdint>
#include <math.h>

// ---------------- problem constants ----------------
#define MM 2048      // num_memories
#define DD 7686      // input size
#define HH 512
#define OO 8
#define NN 8206      // DD + HH + OO
#define KP 7744      // K padded to multiple of 64
#define WROWS 7808   // padded B rows for W^T (61 * 128)
#define BKC 32
#define KCHUNKS (KP / BKC)   // 242

// ---------------- small PTX helpers ----------------
__device__ __forceinline__ uint32_t smem_to_u32(const void* p) {
    uint32_t a;
    asm("{ .reg .u64 t; cvta.to.shared.u64 t, %1; cvt.u32.u64 %0, t; }"
        : "=r"(a) : "l"(p));
    return a;
}

__device__ __forceinline__ void cpa16(uint32_t s, const void* g) {
    asm volatile("cp.async.cg.shared.global [%0], [%1], 16;" :: "r"(s), "l"(g) : "memory");
}
#define CP_COMMIT() asm volatile("cp.async.commit_group;" ::: "memory")

__device__ __forceinline__ void ldsm4(uint32_t (&r)[4], uint32_t addr) {
    asm volatile("ldmatrix.sync.aligned.m8n8.x4.shared.b16 {%0,%1,%2,%3}, [%4];"
                 : "=r"(r[0]), "=r"(r[1]), "=r"(r[2]), "=r"(r[3]) : "r"(addr));
}

__device__ __forceinline__ void mma16816(float (&d)[4], const uint32_t (&a)[4],
                                         const uint32_t b0, const uint32_t b1) {
    asm volatile(
        "mma.sync.aligned.m16n8k16.row.col.f32.bf16.bf16.f32 "
        "{%0,%1,%2,%3}, {%4,%5,%6,%7}, {%8,%9}, {%0,%1,%2,%3};"
        : "+f"(d[0]), "+f"(d[1]), "+f"(d[2]), "+f"(d[3])
        : "r"(a[0]), "r"(a[1]), "r"(a[2]), "r"(a[3]), "r"(b0), "r"(b1));
}

// SW64 swizzle for 64B-wide smem rows (conflict-free ldmatrix)
__device__ __forceinline__ uint32_t sw_off(int row, int c) {
    uint32_t o = (uint32_t)(row * 64 + c * 16);
    return o ^ ((o >> 3) & 0x30);
}

// ---------------- device scratch ----------------
__device__ __nv_bfloat16 g_ihi[(size_t)MM * KP];
__device__ __nv_bfloat16 g_ilo[(size_t)MM * KP];
__device__ __nv_bfloat16 g_wtqhi[(size_t)WROWS * KP];
__device__ __nv_bfloat16 g_wtqlo[(size_t)WROWS * KP];
__device__ __nv_bfloat16 g_wtkhi[(size_t)WROWS * KP];
__device__ __nv_bfloat16 g_wtklo[(size_t)WROWS * KP];
__device__ __nv_bfloat16 g_qhi[(size_t)MM * KP];
__device__ __nv_bfloat16 g_qlo[(size_t)MM * KP];
__device__ __nv_bfloat16 g_khi[(size_t)MM * KP];
__device__ __nv_bfloat16 g_klo[(size_t)MM * KP];
__device__ float g_scores[(size_t)MM * MM];
__device__ float g_cs_part[16 * MM];
__device__ float g_colsum[MM];
__device__ float g_part[16 * DD];
__device__ float g_u[DD];
__device__ float g_context[DD];
__device__ float g_s1_part[61 * (HH + OO)];
__device__ float g_vals1[HH + OO];
__device__ float g_s2_part[32 * OO];

// ---------------- split fp32 -> bf16 hi/lo, pad cols to KP (16B stores) ---------
__global__ void split_pad(const float* __restrict__ x,
                          __nv_bfloat16* __restrict__ hi,
                          __nv_bfloat16* __restrict__ lo, int cols)
{
    int c = (blockIdx.x * 256 + threadIdx.x) * 8;
    if (c >= KP) return;
    int r = blockIdx.y;
    const float* xr = x + (size_t)r * cols;
    uint32_t hw[4], lw[4];
    #pragma unroll
    for (int j = 0; j < 4; ++j) {
        float v0 = (c + 2*j     < cols) ? xr[c + 2*j]     : 0.f;
        float v1 = (c + 2*j + 1 < cols) ? xr[c + 2*j + 1] : 0.f;
        __nv_bfloat16 h0 = __float2bfloat16(v0);
        __nv_bfloat16 h1 = __float2bfloat16(v1);
        __nv_bfloat162 hp; hp.x = h0; hp.y = h1;
        __nv_bfloat162 lp;
        lp.x = __float2bfloat16(v0 - __bfloat162float(h0));
        lp.y = __float2bfloat16(v1 - __bfloat162float(h1));
        hw[j] = *(uint32_t*)&hp;
        lw[j] = *(uint32_t*)&lp;
    }
    *(uint4*)(hi + (size_t)r * KP + c) = make_uint4(hw[0], hw[1], hw[2], hw[3]);
    *(uint4*)(lo + (size_t)r * KP + c) = make_uint4(lw[0], lw[1], lw[2], lw[3]);
}

// ---------------- transpose + split: W[k][n] -> Wt[n][k] bf16 hi/lo -------------
// 64k x 32n tiles, 256 threads, 16B uint4 stores along k. gridDim.z selects
// (Wq -> T1) vs (Wk -> T2).
__global__ void transpose_split2(const float* __restrict__ W1, const float* __restrict__ W2,
                                 __nv_bfloat16* __restrict__ T1hi, __nv_bfloat16* __restrict__ T1lo,
                                 __nv_bfloat16* __restrict__ T2hi, __nv_bfloat16* __restrict__ T2lo)
{
    __shared__ float s[64][33];
    const int t = threadIdx.x;
    const int n0 = blockIdx.x * 32;
    const int k0 = blockIdx.y * 64;
    const float* W = (blockIdx.z == 0) ? W1 : W2;
    __nv_bfloat16* Thi = (blockIdx.z == 0) ? T1hi : T2hi;
    __nv_bfloat16* Tlo = (blockIdx.z == 0) ? T1lo : T2lo;

    #pragma unroll
    for (int i = 0; i < 8; ++i) {
        int idx = i * 256 + t;
        int kl = idx >> 5, nl = idx & 31;
        int k = k0 + kl, n = n0 + nl;
        s[kl][nl] = (k < DD && n < DD) ? W[(size_t)k * DD + n] : 0.f;
    }
    __syncthreads();

    const int a = t >> 3;          // n-local 0..31
    const int g = (t & 7) * 8;     // k-group
    uint32_t hw[4], lw[4];
    #pragma unroll
    for (int j = 0; j < 4; ++j) {
        float v0 = s[g + 2*j][a];
        float v1 = s[g + 2*j + 1][a];
        __nv_bfloat16 h0 = __float2bfloat16(v0);
        __nv_bfloat16 h1 = __float2bfloat16(v1);
        __nv_bfloat162 hp; hp.x = h0; hp.y = h1;
        __nv_bfloat162 lp;
        lp.x = __float2bfloat16(v0 - __bfloat162float(h0));
        lp.y = __float2bfloat16(v1 - __bfloat162float(h1));
        hw[j] = *(uint32_t*)&hp;
        lw[j] = *(uint32_t*)&lp;
    }
    size_t off = (size_t)(n0 + a) * KP + (k0 + g);
    *(uint4*)(Thi + off) = make_uint4(hw[0], hw[1], hw[2], hw[3]);
    *(uint4*)(Tlo + off) = make_uint4(lw[0], lw[1], lw[2], lw[3]);
}

// ---------------- bf16x3 mma.sync GEMM, CTA tile 128x128, 4 warps ---------------
// Dual-B dispatch (q & k fused). Term-major passes with fragment ldsm
// interleaved into the mma stream, and the NEXT-chunk cp.async issue deferred
// into pass-2/pass-3 slack (off the chunk-head critical path). Per-accumulator
// operation sequence unchanged => bit-identical results.  (round-12 winner)
#define T_AHI 0
#define T_ALO 8192
#define T_BHI 16384
#define T_BLO 24576
#define STAGE_BYTES 32768
#define NSTAGE 3
#define SMEM_GEMM (NSTAGE * STAGE_BYTES)   // 98304

__global__ __launch_bounds__(128, 2)
void tc_gemm(const __nv_bfloat16* __restrict__ Ahi, const __nv_bfloat16* __restrict__ Alo,
             const __nv_bfloat16* __restrict__ B1hi, const __nv_bfloat16* __restrict__ B1lo,
             const __nv_bfloat16* __restrict__ B2hi, const __nv_bfloat16* __restrict__ B2lo,
             const float* __restrict__ bias1, const float* __restrict__ bias2,
             int nsplit, float scale,
             float* __restrict__ Cf, int Cld,
             __nv_bfloat16* __restrict__ C1hi, __nv_bfloat16* __restrict__ C1lo,
             __nv_bfloat16* __restrict__ C2hi, __nv_bfloat16* __restrict__ C2lo)
{
    extern __shared__ char smem[];
    const uint32_t sb = smem_to_u32(smem);
    const int t   = threadIdx.x;
    const int wid = t >> 5;
    const int lid = t & 31;
    const int m0 = blockIdx.y * 128;

    const __nv_bfloat16 *Bhi, *Blo;
    const float* bias;
    __nv_bfloat16 *Chi, *Clo;
    int n0;
    if ((int)blockIdx.x < nsplit) {
        n0 = blockIdx.x * 128;
        Bhi = B1hi; Blo = B1lo; bias = bias1; Chi = C1hi; Clo = C1lo;
    } else {
        n0 = (blockIdx.x - nsplit) * 128;
        Bhi = B2hi; Blo = B2lo; bias = bias2; Chi = C2hi; Clo = C2lo;
    }

    const int rl = t >> 2;
    const int cl = t & 3;
    const uint32_t soR[4] = { sw_off(rl, cl), sw_off(rl + 32, cl),
                              sw_off(rl + 64, cl), sw_off(rl + 96, cl) };

    float acc[4][8][4];
    #pragma unroll
    for (int a = 0; a < 4; ++a)
        #pragma unroll
        for (int b = 0; b < 8; ++b)
            #pragma unroll
            for (int c = 0; c < 4; ++c) acc[a][b][c] = 0.f;

    const char* pAhi = (const char*)Ahi;
    const char* pAlo = (const char*)Alo;
    const char* pBhi = (const char*)Bhi;
    const char* pBlo = (const char*)Blo;

    // full-burst loader (used only for the two priming stages)
    auto load_stage = [&](int kc, int slot) {
        const int k0 = kc * BKC;
        const uint32_t st = sb + slot * STAGE_BYTES;
        #pragma unroll
        for (int i = 0; i < 4; ++i) {
            const int r = rl + 32 * i;
            size_t ga = (((size_t)(m0 + r) * KP + k0 + cl * 8) << 1);
            size_t gb = (((size_t)(n0 + r) * KP + k0 + cl * 8) << 1);
            cpa16(st + T_AHI + soR[i], pAhi + ga);
            cpa16(st + T_ALO + soR[i], pAlo + ga);
            cpa16(st + T_BHI + soR[i], pBhi + gb);
            cpa16(st + T_BLO + soR[i], pBlo + gb);
        }
        CP_COMMIT();
    };

    const int wm = wid >> 1;       // 0..1 (m offset 64)
    const int wn = wid & 1;        // 0..1 (n offset 64)
    const int lrow = lid & 15;
    const int lcg  = lid >> 4;     // 0..1

    load_stage(0, 0);
    load_stage(1, 1);

    int slot = 0;                  // kc % 3
    int nslot = 2;                 // (kc+2) % 3
    for (int kc = 0; kc < KCHUNKS; ++kc) {
        asm volatile("cp.async.wait_group 1;" ::: "memory");
        __syncthreads();

        const bool pf = (kc + 2 < KCHUNKS);
        const int pk0 = (kc + 2) * BKC;
        const uint32_t pst = sb + nslot * STAGE_BYTES;
        const uint32_t st = sb + slot * STAGE_BYTES;
        slot = (slot == 2) ? 0 : slot + 1;
        nslot = (nslot == 2) ? 0 : nslot + 1;

        // deferred prefetch slice for chunk kc+2 (issued inside mma slack)
        auto load_slice = [&](int i) {
            if (pf) {
                const int r = rl + 32 * i;
                size_t ga = (((size_t)(m0 + r) * KP + pk0 + cl * 8) << 1);
                size_t gb = (((size_t)(n0 + r) * KP + pk0 + cl * 8) << 1);
                cpa16(pst + T_AHI + soR[i], pAhi + ga);
                cpa16(pst + T_ALO + soR[i], pAlo + ga);
                cpa16(pst + T_BHI + soR[i], pBhi + gb);
                cpa16(pst + T_BLO + soR[i], pBlo + gb);
            }
        };

        #pragma unroll
        for (int ks = 0; ks < 2; ++ks) {
            const int ccol = ks * 2 + lcg;
            uint32_t ahi[4][4], alo[4][4];
            uint32_t bhi[8][2], blo[8][2];

            // minimal preload: A-hi fragments + first B-hi pair
            #pragma unroll
            for (int mt = 0; mt < 4; ++mt)
                ldsm4(ahi[mt], st + T_AHI + sw_off(wm * 64 + mt * 16 + lrow, ccol));
            {
                uint32_t r[4];
                ldsm4(r, st + T_BHI + sw_off(wn * 64 + lrow, ccol));
                bhi[0][0] = r[0]; bhi[0][1] = r[2];
                bhi[1][0] = r[1]; bhi[1][1] = r[3];
            }

            // pass 1: hi*hi  (prefetch remaining bhi + all blo under mma)
            #pragma unroll
            for (int p = 0; p < 4; ++p) {
                if (p < 3) {
                    uint32_t r[4];
                    ldsm4(r, st + T_BHI + sw_off(wn * 64 + (p + 1) * 16 + lrow, ccol));
                    bhi[2*p+2][0] = r[0]; bhi[2*p+2][1] = r[2];
                    bhi[2*p+3][0] = r[1]; bhi[2*p+3][1] = r[3];
                }
                {
                    uint32_t r[4];
                    ldsm4(r, st + T_BLO + sw_off(wn * 64 + p * 16 + lrow, ccol));
                    blo[2*p][0] = r[0]; blo[2*p][1] = r[2];
                    blo[2*p+1][0] = r[1]; blo[2*p+1][1] = r[3];
                }
                #pragma unroll
                for (int mt = 0; mt < 4; ++mt) {
                    mma16816(acc[mt][2*p],     ahi[mt], bhi[2*p][0],   bhi[2*p][1]);
                    mma16816(acc[mt][2*p + 1], ahi[mt], bhi[2*p+1][0], bhi[2*p+1][1]);
                }
            }

            // pass 2: hi*lo  (prefetch alo under mma; inject cp.async slice)
            load_slice(ks * 2);
            #pragma unroll
            for (int p = 0; p < 4; ++p) {
                ldsm4(alo[p], st + T_ALO + sw_off(wm * 64 + p * 16 + lrow, ccol));
                #pragma unroll
                for (int mt = 0; mt < 4; ++mt) {
                    mma16816(acc[mt][2*p],     ahi[mt], blo[2*p][0],   blo[2*p][1]);
                    mma16816(acc[mt][2*p + 1], ahi[mt], blo[2*p+1][0], blo[2*p+1][1]);
                }
            }

            // pass 3: lo*hi  (pure mma; inject second cp.async slice)
            load_slice(ks * 2 + 1);
            #pragma unroll
            for (int mt = 0; mt < 4; ++mt)
                #pragma unroll
                for (int q = 0; q < 8; ++q)
                    mma16816(acc[mt][q], alo[mt], bhi[q][0], bhi[q][1]);
        }

        CP_COMMIT();   // one group per chunk (empty near the tail)
    }

    // ---- epilogue ----
    const int g  = lid >> 2;
    const int t4 = lid & 3;
    #pragma unroll
    for (int mt = 0; mt < 4; ++mt) {
        #pragma unroll
        for (int nt = 0; nt < 8; ++nt) {
            const int m = m0 + wm * 64 + mt * 16 + g;
            const int n = n0 + wn * 64 + nt * 8 + t4 * 2;
            float d0 = acc[mt][nt][0], d1 = acc[mt][nt][1];
            float d2 = acc[mt][nt][2], d3 = acc[mt][nt][3];
            if (Cf) {
                if (n + 1 < Cld) {
                    float2 v0 = make_float2(d0 * scale, d1 * scale);
                    float2 v1 = make_float2(d2 * scale, d3 * scale);
                    *(float2*)(Cf + (size_t)m * Cld + n) = v0;
                    *(float2*)(Cf + (size_t)(m + 8) * Cld + n) = v1;
                }
            } else {
                if (n < KP) {
                    float b0 = (n     < DD) ? bias[n]     : 0.f;
                    float b1 = (n + 1 < DD) ? bias[n + 1] : 0.f;
                    float v0 = (n     < DD) ? d0 + b0 : 0.f;
                    float v1 = (n + 1 < DD) ? d1 + b1 : 0.f;
                    float v2 = (n     < DD) ? d2 + b0 : 0.f;
                    float v3 = (n + 1 < DD) ? d3 + b1 : 0.f;
                    __nv_bfloat16 h0 = __float2bfloat16(v0);
                    __nv_bfloat16 h1 = __float2bfloat16(v1);
                    __nv_bfloat16 h2 = __float2bfloat16(v2);
                    __nv_bfloat16 h3 = __float2bfloat16(v3);
                    __nv_bfloat162 hp0; hp0.x = h0; hp0.y = h1;
                    __nv_bfloat162 hp1; hp1.x = h2; hp1.y = h3;
                    __nv_bfloat162 lp0;
                    lp0.x = __float2bfloat16(v0 - __bfloat162float(h0));
                    lp0.y = __float2bfloat16(v1 - __bfloat162float(h1));
                    __nv_bfloat162 lp1;
                    lp1.x = __float2bfloat16(v2 - __bfloat162float(h2));
                    lp1.y = __float2bfloat16(v3 - __bfloat162float(h3));
                    *(__nv_bfloat162*)(Chi + (size_t)m * KP + n) = hp0;
                    *(__nv_bfloat162*)(Chi + (size_t)(m + 8) * KP + n) = hp1;
                    *(__nv_bfloat162*)(Clo + (size_t)m * KP + n) = lp0;
                    *(__nv_bfloat162*)(Clo + (size_t)(m + 8) * KP + n) = lp1;
                }
            }
        }
    }
}

// ---------------- row softmax (in place), row length MM ------------------------
__global__ void softmax_rows(float* __restrict__ S)
{
    const int row = blockIdx.x;
    const int t = threadIdx.x;
    float* r = S + (size_t)row * MM;
    float v[8];
    #pragma unroll
    for (int i = 0; i < 8; ++i) v[i] = r[i * 256 + t];

    float mx = v[0];
    #pragma unroll
    for (int i = 1; i < 8; ++i) mx = fmaxf(mx, v[i]);

    __shared__ float sh[32];
    #pragma unroll
    for (int o = 16; o > 0; o >>= 1) mx = fmaxf(mx, __shfl_xor_sync(0xffffffff, mx, o));
    if ((t & 31) == 0) sh[t >> 5] = mx;
    __syncthreads();
    if (t < 32) {
        float m = (t < 8) ? sh[t] : -INFINITY;
        #pragma unroll
        for (int o = 4; o > 0; o >>= 1) m = fmaxf(m, __shfl_xor_sync(0xffffffff, m, o));
        sh[0] = m;
    }
    __syncthreads();
    mx = sh[0];
    __syncthreads();

    float sum = 0.f;
    #pragma unroll
    for (int i = 0; i < 8; ++i) { v[i] = expf(v[i] - mx); sum += v[i]; }
    #pragma unroll
    for (int o = 16; o > 0; o >>= 1) sum += __shfl_xor_sync(0xffffffff, sum, o);
    if ((t & 31) == 0) sh[t >> 5] = sum;
    __syncthreads();
    if (t < 32) {
        float s = (t < 8) ? sh[t] : 0.f;
        #pragma unroll
        for (int o = 4; o > 0; o >>= 1) s += __shfl_xor_sync(0xffffffff, s, o);
        sh[0] = s;
    }
    __syncthreads();
    float inv = 1.f / sh[0];
    #pragma unroll
    for (int i = 0; i < 8; ++i) r[i * 256 + t] = v[i] * inv;
}

// ---------------- column sums of P ----------------
__global__ void colsum_part(const float* __restrict__ P)
{
    int j = blockIdx.x * 256 + threadIdx.x;
    int r0 = blockIdx.y * 128;
    float acc = 0.f;
    for (int r = 0; r < 128; ++r) acc += P[(size_t)(r0 + r) * MM + j];
    g_cs_part[blockIdx.y * MM + j] = acc;
}

__global__ void colsum_reduce()
{
    int j = blockIdx.x * 256 + threadIdx.x;
    float acc = 0.f;
    #pragma unroll
    for (int c = 0; c < 16; ++c) acc += g_cs_part[c * MM + j];
    g_colsum[j] = acc;
}

// ---------------- u = (colsum @ inp) / M ----------------
__global__ void u_part(const float* __restrict__ X)
{
    int j = blockIdx.x * 256 + threadIdx.x;
    if (j >= DD) return;
    int r0 = blockIdx.y * 128;
    float acc = 0.f;
    for (int r = 0; r < 128; ++r) {
        int l = r0 + r;
        acc += g_colsum[l] * X[(size_t)l * DD + j];
    }
    g_part[blockIdx.y * DD + j] = acc;
}

__global__ void u_reduce()
{
    int j = blockIdx.x * 256 + threadIdx.x;
    if (j >= DD) return;
    float acc = 0.f;
    #pragma unroll
    for (int c = 0; c < 16; ++c) acc += g_part[c * DD + j];
    g_u[j] = acc * (1.0f / (float)MM);
}

// ---------------- context = u @ Wv + bv ----------------
__global__ void ctx2_part(const float* __restrict__ Wv)
{
    int j = blockIdx.x * 256 + threadIdx.x;
    if (j >= DD) return;
    int i0 = blockIdx.y * 481;
    float acc = 0.f;
    for (int r = 0; r < 481; ++r) {
        int i = i0 + r;
        if (i < DD) acc += g_u[i] * Wv[(size_t)i * DD + j];
    }
    g_part[blockIdx.y * DD + j] = acc;
}

__global__ void ctx2_reduce(const float* __restrict__ bv)
{
    int j = blockIdx.x * 256 + threadIdx.x;
    if (j >= DD) return;
    float acc = 0.f;
    #pragma unroll
    for (int c = 0; c < 16; ++c) acc += g_part[c * DD + j];
    g_context[j] = acc + bv[j];
}

// ---------------- sweep 1: cols [DD, NN), rows i<DD ----------------
__global__ void sweep1_part(const float* __restrict__ mu, const float* __restrict__ sig,
                            const float* __restrict__ eps)
{
    int jj = blockIdx.x * 256 + threadIdx.x;
    if (jj >= HH + OO) return;
    int j = DD + jj;
    int i0 = blockIdx.y * 126;
    float acc = 0.f;
    for (int r = 0; r < 126; ++r) {
        int i = i0 + r;
        size_t off = (size_t)i * NN + j;
        acc += g_context[i] * (mu[off] + sig[off] * eps[off]);
    }
    g_s1_part[blockIdx.y * (HH + OO) + jj] = acc;
}

__global__ void sweep1_final(const float* __restrict__ bmu, const float* __restrict__ bsig,
                             const float* __restrict__ epsb)
{
    int jj = blockIdx.x * 256 + threadIdx.x;
    if (jj >= HH + OO) return;
    int j = DD + jj;
    float acc = 0.f;
    for (int c = 0; c < 61; ++c) acc += g_s1_part[c * (HH + OO) + jj];
    g_vals1[jj] = tanhf(acc + bmu[j] + bsig[j] * epsb[j]);
}

// ---------------- sweep 2: cols [DD+HH, NN), all rows ----------------
__global__ void sweep2_part(const float* __restrict__ mu, const float* __restrict__ sig,
                            const float* __restrict__ eps)
{
    const int t = threadIdx.x;
    const int col = t & 7;
    const int lane = t >> 3;
    const int i0 = blockIdx.x * 257;
    const int j = DD + HH + col;
    float acc = 0.f;
    for (int r = lane; r < 257; r += 32) {
        int i = i0 + r;
        if (i < NN) {
            float vi = (i < DD) ? g_context[i] : g_vals1[i - DD];
            size_t off = (size_t)i * NN + j;
            acc += vi * (mu[off] + sig[off] * eps[off]);
        }
    }
    __shared__ float sh[256];
    sh[t] = acc;
    __syncthreads();
    for (int s = 128; s >= 8; s >>= 1) {
        if (t < s) sh[t] += sh[t + s];
        __syncthreads();
    }
    if (t < 8) g_s2_part[blockIdx.x * 8 + t] = sh[t];
}

__global__ void final_out(const float* __restrict__ bmu, const float* __restrict__ bsig,
                          const float* __restrict__ epsb, float* __restrict__ out)
{
    int t = threadIdx.x;
    if (t < OO) {
        float acc = 0.f;
        #pragma unroll
        for (int b = 0; b < 32; ++b) acc += g_s2_part[b * 8 + t];
        int j = DD + HH + t;
        float v = tanhf(acc + bmu[j] + bsig[j] * epsb[j]);
        out[t] = 1.0f / (1.0f + expf(-v));
    }
}

// ---------------- launcher -------------------------------------------------------
extern "C" void kernel_launch(void* const* d_in, const int* in_sizes, int n_in,
                              void* d_out, int out_size)
{
    const float* inp  = (const float*)d_in[0];
    const float* Wq   = (const float*)d_in[1];
    const float* bq   = (const float*)d_in[2];
    const float* Wk   = (const float*)d_in[3];
    const float* bk   = (const float*)d_in[4];
    const float* Wv   = (const float*)d_in[5];
    const float* bv   = (const float*)d_in[6];
    const float* wmu  = (const float*)d_in[7];
    const float* wsig = (const float*)d_in[8];
    const float* bmu  = (const float*)d_in[9];
    const float* bsig = (const float*)d_in[10];
    const float* epsw = (const float*)d_in[11];
    const float* epsb = (const float*)d_in[12];
    float* out = (float*)d_out;

    __nv_bfloat16 *ihi, *ilo, *wtqhi, *wtqlo, *wtkhi, *wtklo;
    __nv_bfloat16 *qhi, *qlo, *khi, *klo;
    float *sc;
    cudaGetSymbolAddress((void**)&ihi,   g_ihi);
    cudaGetSymbolAddress((void**)&ilo,   g_ilo);
    cudaGetSymbolAddress((void**)&wtqhi, g_wtqhi);
    cudaGetSymbolAddress((void**)&wtqlo, g_wtqlo);
    cudaGetSymbolAddress((void**)&wtkhi, g_wtkhi);
    cudaGetSymbolAddress((void**)&wtklo, g_wtklo);
    cudaGetSymbolAddress((void**)&qhi,   g_qhi);
    cudaGetSymbolAddress((void**)&qlo,   g_qlo);
    cudaGetSymbolAddress((void**)&khi,   g_khi);
    cudaGetSymbolAddress((void**)&klo,   g_klo);
    cudaGetSymbolAddress((void**)&sc,    g_scores);

    cudaFuncSetAttribute(tc_gemm, cudaFuncAttributeMaxDynamicSharedMemorySize,
                         SMEM_GEMM);

    const dim3 split_grid((KP / 8 + 255) / 256, MM);
    const dim3 tr_grid(WROWS / 32, KP / 64, 2);
    const dim3 qk_grid(2 * (WROWS / 128), MM / 128);   // 122 x 16 (q & k fused)
    const dim3 sc_grid(MM / 128, MM / 128);            // 16 x 16

    // input split to bf16 hi/lo
    split_pad<<<split_grid, 256>>>(inp, ihi, ilo, DD);

    // transpose+split both weight matrices in one launch
    transpose_split2<<<tr_grid, 256>>>(Wq, Wk, wtqhi, wtqlo, wtkhi, wtklo);

    // q = inp @ Wq + bq  AND  k = inp @ Wk + bk  (one launch, bf16 hi/lo out)
    tc_gemm<<<qk_grid, 128, SMEM_GEMM>>>(ihi, ilo,
                                         wtqhi, wtqlo, wtkhi, wtklo,
                                         bq, bk, WROWS / 128, 1.f,
                                         nullptr, 0, qhi, qlo, khi, klo);

    // scores = q @ k^T / sqrt(D)  (fp32 out)
    tc_gemm<<<sc_grid, 128, SMEM_GEMM>>>(qhi, qlo,
                                         khi, klo, nullptr, nullptr,
                                         nullptr, nullptr, 1 << 20,
                                         rsqrtf((float)DD),
                                         sc, MM, nullptr, nullptr, nullptr, nullptr);

    softmax_rows<<<MM, 256>>>(sc);

    colsum_part<<<dim3(MM / 256, 16), 256>>>(sc);
    colsum_reduce<<<MM / 256, 256>>>();

    // context = ((colsum/M) @ inp) @ Wv + bv
    u_part<<<dim3((DD + 255) / 256, 16), 256>>>(inp);
    u_reduce<<<(DD + 255) / 256, 256>>>();
    ctx2_part<<<dim3((DD + 255) / 256, 16), 256>>>(Wv);
    ctx2_reduce<<<(DD + 255) / 256, 256>>>(bv);

    sweep1_part<<<dim3(3, 61), 256>>>(wmu, wsig, epsw);
    sweep1_final<<<3, 256>>>(bmu, bsig, epsb);

    sweep2_part<<<32, 256>>>(wmu, wsig, epsw);
    final_out<<<1, 32>>>(bmu, bsig, epsb, out);
}